// round 8
// baseline (speedup 1.0000x reference)
#include <cuda_runtime.h>
#include <cstddef>

// GaussianIntegral2D — one-shot, 8-lanes-per-pair, register-resident
// quadrature table, aligned STG.128 outputs. No grid-stride loop, no
// prefetch (R7 showed the prefetch registers clamp occupancy at 34%; 16K
// independent blocks hide latency instead), no LDS in the hot path.
//
// Warp = 4 groups of 8 lanes; group g of warp-quad qid owns pair
// p = 4*qid + g, so phi = p&1 = g&1 is fixed per thread and each thread's
// 6 quadrature points (u = 2*(s+8k)+phi) live in registers.
// Row layout (392 B = 8 + 24*16): phi=0 -> 24 aligned float4 + float2 tail
// at +384; phi=1 -> float2 head + 24 aligned float4 at +8.

#define LOG2_2PI_F 2.651496129472319f           // log2(2*pi)
#define NEG_HALF_LOG2E_F (-0.7213475204444817f) // -0.5 * log2(e)

static constexpr int Q   = 49;
static constexpr int TPB = 256;

__global__ void __launch_bounds__(TPB, 4)
gauss_integral_kernel(const float* __restrict__ means,   // [P,2]
                      const float* __restrict__ covars,  // [P,4]
                      const float* __restrict__ rots,    // [P,4]
                      const float* __restrict__ trans,   // [P,2]
                      const float* __restrict__ eta,     // [2,Q]
                      const float* __restrict__ wts,     // [Q]
                      float* __restrict__ out_pts,       // [P,Q,2]
                      float* __restrict__ out_int,       // [P]
                      int npair)
{
    const int tid  = threadIdx.x;
    const int lane = tid & 31;
    const int s    = lane & 7;       // slot phase within group
    const int g    = lane >> 3;      // group within warp
    const int phi  = g & 1;          // pair parity — fixed per thread

    const int p = ((blockIdx.x * TPB + tid) >> 5) * 4 + g;
    if (p >= npair) return;          // group-uniform

    // Register-resident quadrature data: 6 points per thread (2 per slot).
    float ex[6], ey[6], lw[6];
    #pragma unroll
    for (int k = 0; k < 3; ++k) {
        const int u = 2 * (s + 8 * k) + phi;     // 0..47 (phi=0) / 1..48 (phi=1)
        ex[2*k]   = __ldg(eta + u);     ey[2*k]   = __ldg(eta + Q + u);
        ex[2*k+1] = __ldg(eta + u + 1); ey[2*k+1] = __ldg(eta + Q + u + 1);
        lw[2*k]   = __log2f(__ldg(wts + u));
        lw[2*k+1] = __log2f(__ldg(wts + u + 1));
    }
    // Tail point (s==0 lane only): q=0 for phi=1, q=48 for phi=0.
    const int qt = phi ? 0 : Q - 1;
    const float ext = __ldg(eta + qt), eyt = __ldg(eta + Q + qt);
    const float lwt = __log2f(__ldg(wts + qt));

    // Per-pair params: 8 lanes/group load the same address (L1 broadcast).
    const float2 m = reinterpret_cast<const float2*>(means)[p];
    const float4 c = reinterpret_cast<const float4*>(covars)[p]; // c00 c01 c10 c11
    const float4 r = reinterpret_cast<const float4*>(rots)[p];
    const float2 t = reinterpret_cast<const float2*>(trans)[p];

    const float det   = c.x * c.w - c.y * c.z;
    const float kinv2 = NEG_HALF_LOG2E_F * __frcp_rn(det);
    const float base2 = fmaf(-0.5f, __log2f(det), -LOG2_2PI_F);
    const float csum  = c.y + c.z;

    char* const outb = reinterpret_cast<char*>(out_pts)
                     + (size_t)p * (size_t)(8 * Q);

    float acc0 = 0.0f, acc1 = 0.0f;

    #pragma unroll
    for (int k = 0; k < 3; ++k) {
        const int j = s + 8 * k;                 // float4 slot 0..23
        const float px0 = fmaf(r.x, ex[2*k],   fmaf(r.y, ey[2*k],   t.x));
        const float py0 = fmaf(r.z, ex[2*k],   fmaf(r.w, ey[2*k],   t.y));
        const float px1 = fmaf(r.x, ex[2*k+1], fmaf(r.y, ey[2*k+1], t.x));
        const float py1 = fmaf(r.z, ex[2*k+1], fmaf(r.w, ey[2*k+1], t.y));

        __stcs(reinterpret_cast<float4*>(outb + 8 * phi + 16 * j),
               make_float4(px0, py0, px1, py1));  // 16B-aligned STG.128

        float dx = px0 - m.x, dy = py0 - m.y;
        float quad = fmaf(c.w * dx, dx, fmaf(-csum * dx, dy, c.x * dy * dy));
        acc0 += exp2f(fmaf(kinv2, quad, base2 + lw[2*k]));

        dx = px1 - m.x; dy = py1 - m.y;
        quad = fmaf(c.w * dx, dx, fmaf(-csum * dx, dy, c.x * dy * dy));
        acc1 += exp2f(fmaf(kinv2, quad, base2 + lw[2*k+1]));
    }

    // Scalar tail point (one per pair).
    if (s == 0) {
        const float px = fmaf(r.x, ext, fmaf(r.y, eyt, t.x));
        const float py = fmaf(r.z, ext, fmaf(r.w, eyt, t.y));
        __stcs(reinterpret_cast<float2*>(outb + (phi ? 0 : 8 * (Q - 1))),
               make_float2(px, py));
        const float dx = px - m.x, dy = py - m.y;
        const float quad = fmaf(c.w * dx, dx,
                           fmaf(-csum * dx, dy, c.x * dy * dy));
        acc0 += exp2f(fmaf(kinv2, quad, base2 + lwt));
    }

    // Reduce over the 8 lanes of this group.
    float acc = acc0 + acc1;
    const unsigned gmask = 0xFFu << (g * 8);
    acc += __shfl_down_sync(gmask, acc, 4, 8);
    acc += __shfl_down_sync(gmask, acc, 2, 8);
    acc += __shfl_down_sync(gmask, acc, 1, 8);

    if (s == 0)
        out_int[p] = fminf(fmaxf(acc, 0.0f), 1.0f);  // 4 lanes -> 16B coalesced
}

extern "C" void kernel_launch(void* const* d_in, const int* in_sizes, int n_in,
                              void* d_out, int out_size)
{
    const float* means  = (const float*)d_in[0];
    const float* covars = (const float*)d_in[1];
    const float* rots   = (const float*)d_in[2];
    const float* trans  = (const float*)d_in[3];
    const float* eta    = (const float*)d_in[4];
    const float* wts    = (const float*)d_in[5];

    const int npair = in_sizes[0] / 2;

    float* out_pts = (float*)d_out;
    float* out_int = out_pts + (size_t)npair * (size_t)(2 * Q);

    // 4 pairs per warp, 8 warps per block -> 32 pairs per block.
    const int blocks = (npair + 31) / 32;
    gauss_integral_kernel<<<blocks, TPB>>>(
        means, covars, rots, trans, eta, wts, out_pts, out_int, npair);
}

// round 9
// speedup vs baseline: 1.1960x; 1.1960x over previous
#include <cuda_runtime.h>
#include <cstddef>

// GaussianIntegral2D — R7 structure (grid-stride + param prefetch +
// register-resident quadrature table + aligned STG.128), refined:
//   * TPB=128: 73-reg kernel packs 7 blocks/SM (28 warps) vs 3x8=24 at 256.
//   * Output pointers advanced by a loop-invariant stride (no per-iter
//     64-bit p*392 IMAD chains).
//
// Warp = 4 groups of 8 lanes; group g of quad qid owns pair p = 4*qid+g,
// so phi = p&1 = g&1 is fixed per thread and the 6 quadrature points
// (u = 2*(s+8k)+phi) are loop-invariant registers.

#define LOG2_2PI_F 2.651496129472319f           // log2(2*pi)
#define NEG_HALF_LOG2E_F (-0.7213475204444817f) // -0.5 * log2(e)

static constexpr int Q   = 49;
static constexpr int TPB = 128;
static constexpr int ROW_B = 8 * Q;             // 392 bytes per pair row

struct Params { float2 m, t; float4 c, r; };

__device__ __forceinline__ void load_params(
    const float* __restrict__ means, const float* __restrict__ covars,
    const float* __restrict__ rots,  const float* __restrict__ trans,
    int p, Params& P)
{
    P.m = reinterpret_cast<const float2*>(means)[p];
    P.c = reinterpret_cast<const float4*>(covars)[p];   // c00 c01 c10 c11
    P.r = reinterpret_cast<const float4*>(rots)[p];
    P.t = reinterpret_cast<const float2*>(trans)[p];
}

__global__ void __launch_bounds__(TPB)
gauss_integral_kernel(const float* __restrict__ means,   // [P,2]
                      const float* __restrict__ covars,  // [P,4]
                      const float* __restrict__ rots,    // [P,4]
                      const float* __restrict__ trans,   // [P,2]
                      const float* __restrict__ eta,     // [2,Q]
                      const float* __restrict__ wts,     // [Q]
                      float* __restrict__ out_pts,       // [P,Q,2]
                      float* __restrict__ out_int,       // [P]
                      int npair)
{
    const int tid  = threadIdx.x;
    const int lane = tid & 31;
    const int s    = lane & 7;       // slot phase within group
    const int g    = lane >> 3;      // group within warp
    const int phi  = g & 1;          // pair parity — fixed per thread

    // Register-resident quadrature data: 6 points per thread (2 per slot).
    float ex[6], ey[6], lw[6];
    #pragma unroll
    for (int k = 0; k < 3; ++k) {
        const int u = 2 * (s + 8 * k) + phi;     // 0..47 (phi=0) / 1..48 (phi=1)
        ex[2*k]   = __ldg(eta + u);     ey[2*k]   = __ldg(eta + Q + u);
        ex[2*k+1] = __ldg(eta + u + 1); ey[2*k+1] = __ldg(eta + Q + u + 1);
        lw[2*k]   = __log2f(__ldg(wts + u));
        lw[2*k+1] = __log2f(__ldg(wts + u + 1));
    }
    // Tail point (s==0 lane only): q=0 for phi=1, q=48 for phi=0.
    const int qt = phi ? 0 : Q - 1;
    const float ext = __ldg(eta + qt), eyt = __ldg(eta + Q + qt);
    const float lwt = __log2f(__ldg(wts + qt));

    const int warp_g = (blockIdx.x * TPB + tid) >> 5;
    const int nwarp  = (gridDim.x * TPB) >> 5;
    const int nquad  = (npair + 3) >> 2;

    int  qid   = warp_g;
    bool valid = (qid < nquad);
    int  p     = qid * 4 + g;

    // Loop-invariant pointer strides (hoisted address math).
    const size_t    step_b = (size_t)(4 * nwarp) * (size_t)ROW_B;
    char*           outb   = reinterpret_cast<char*>(out_pts)
                           + (size_t)p * (size_t)ROW_B;
    float*          oint   = out_int + p;
    const int       pstep  = 4 * nwarp;

    Params P;
    if (valid && p < npair)
        load_params(means, covars, rots, trans, p, P);

    while (valid) {
        // ---- prefetch next iteration's params ----
        const int  qn    = qid + nwarp;
        const bool vnext = (qn < nquad);
        const int  pn    = p + pstep;
        Params Pn;
        if (vnext && pn < npair)
            load_params(means, covars, rots, trans, pn, Pn);

        // ---- compute current pair ----
        if (p < npair) {
            const float det   = P.c.x * P.c.w - P.c.y * P.c.z;
            const float kinv2 = NEG_HALF_LOG2E_F * __frcp_rn(det);
            const float base2 = fmaf(-0.5f, __log2f(det), -LOG2_2PI_F);
            const float csum  = P.c.y + P.c.z;

            float acc0 = 0.0f, acc1 = 0.0f;

            #pragma unroll
            for (int k = 0; k < 3; ++k) {
                const int j = s + 8 * k;          // float4 slot 0..23
                const float px0 = fmaf(P.r.x, ex[2*k],   fmaf(P.r.y, ey[2*k],   P.t.x));
                const float py0 = fmaf(P.r.z, ex[2*k],   fmaf(P.r.w, ey[2*k],   P.t.y));
                const float px1 = fmaf(P.r.x, ex[2*k+1], fmaf(P.r.y, ey[2*k+1], P.t.x));
                const float py1 = fmaf(P.r.z, ex[2*k+1], fmaf(P.r.w, ey[2*k+1], P.t.y));

                __stcs(reinterpret_cast<float4*>(outb + 8 * phi + 16 * j),
                       make_float4(px0, py0, px1, py1));   // 16B-aligned STG.128

                float dx = px0 - P.m.x, dy = py0 - P.m.y;
                float quad = fmaf(P.c.w * dx, dx,
                             fmaf(-csum * dx, dy, P.c.x * dy * dy));
                acc0 += exp2f(fmaf(kinv2, quad, base2 + lw[2*k]));

                dx = px1 - P.m.x; dy = py1 - P.m.y;
                quad = fmaf(P.c.w * dx, dx,
                       fmaf(-csum * dx, dy, P.c.x * dy * dy));
                acc1 += exp2f(fmaf(kinv2, quad, base2 + lw[2*k+1]));
            }

            // Scalar tail point (one per pair).
            if (s == 0) {
                const float px = fmaf(P.r.x, ext, fmaf(P.r.y, eyt, P.t.x));
                const float py = fmaf(P.r.z, ext, fmaf(P.r.w, eyt, P.t.y));
                __stcs(reinterpret_cast<float2*>(outb + (phi ? 0 : 8 * (Q - 1))),
                       make_float2(px, py));
                const float dx = px - P.m.x, dy = py - P.m.y;
                const float quad = fmaf(P.c.w * dx, dx,
                                   fmaf(-csum * dx, dy, P.c.x * dy * dy));
                acc0 += exp2f(fmaf(kinv2, quad, base2 + lwt));
            }

            // Reduce over the 8 lanes of this group.
            float acc = acc0 + acc1;
            const unsigned gmask = 0xFFu << (g * 8);
            acc += __shfl_down_sync(gmask, acc, 4, 8);
            acc += __shfl_down_sync(gmask, acc, 2, 8);
            acc += __shfl_down_sync(gmask, acc, 1, 8);

            if (s == 0)
                *oint = fminf(fmaxf(acc, 0.0f), 1.0f);
        }

        P = Pn; qid = qn; p = pn; valid = vnext;
        outb += step_b; oint += pstep;
    }
}

extern "C" void kernel_launch(void* const* d_in, const int* in_sizes, int n_in,
                              void* d_out, int out_size)
{
    const float* means  = (const float*)d_in[0];
    const float* covars = (const float*)d_in[1];
    const float* rots   = (const float*)d_in[2];
    const float* trans  = (const float*)d_in[3];
    const float* eta    = (const float*)d_in[4];
    const float* wts    = (const float*)d_in[5];

    const int npair = in_sizes[0] / 2;

    float* out_pts = (float*)d_out;
    float* out_int = out_pts + (size_t)npair * (size_t)(2 * Q);

    // ~8 grid-stride iterations per warp at P = 524288.
    const int blocks = 4096;     // 4096 * 128 threads = 16384 warps
    gauss_integral_kernel<<<blocks, TPB>>>(
        means, covars, rots, trans, eta, wts, out_pts, out_int, npair);
}

// round 10
// speedup vs baseline: 1.2062x; 1.0086x over previous
#include <cuda_runtime.h>
#include <cstddef>

// GaussianIntegral2D — R9 structure (grid-stride + param prefetch +
// register-resident quadrature table + aligned STG.128, TPB=128), with the
// exponent evaluated as a quadratic polynomial in (px,py):
//   arg = Qa*px^2 + Qb*px*py + Qc*py^2 + D*px + E*py + F   (5 FMA Horner)
// and normalization pulled out of the exponent:
//   integral = scale * sum_q w_q * 2^arg_q,  scale = rsqrt(det)/(2*pi).
// Per-point cost 16 -> 11 ops; no log2/lw in the per-point path at all.

#define NEG_HALF_LOG2E_F (-0.7213475204444817f) // -0.5 * log2(e)
#define INV_2PI_F 0.15915494309189535f          // 1/(2*pi)

static constexpr int Q     = 49;
static constexpr int TPB   = 128;
static constexpr int ROW_B = 8 * Q;             // 392 bytes per pair row

struct Params { float2 m, t; float4 c, r; };

__device__ __forceinline__ void load_params(
    const float* __restrict__ means, const float* __restrict__ covars,
    const float* __restrict__ rots,  const float* __restrict__ trans,
    int p, Params& P)
{
    P.m = reinterpret_cast<const float2*>(means)[p];
    P.c = reinterpret_cast<const float4*>(covars)[p];   // c00 c01 c10 c11
    P.r = reinterpret_cast<const float4*>(rots)[p];
    P.t = reinterpret_cast<const float2*>(trans)[p];
}

__global__ void __launch_bounds__(TPB)
gauss_integral_kernel(const float* __restrict__ means,   // [P,2]
                      const float* __restrict__ covars,  // [P,4]
                      const float* __restrict__ rots,    // [P,4]
                      const float* __restrict__ trans,   // [P,2]
                      const float* __restrict__ eta,     // [2,Q]
                      const float* __restrict__ wts,     // [Q]
                      float* __restrict__ out_pts,       // [P,Q,2]
                      float* __restrict__ out_int,       // [P]
                      int npair)
{
    const int tid  = threadIdx.x;
    const int lane = tid & 31;
    const int s    = lane & 7;       // slot phase within group
    const int g    = lane >> 3;      // group within warp
    const int phi  = g & 1;          // pair parity — fixed per thread

    // Register-resident quadrature data: 6 points per thread (2 per slot).
    float ex[6], ey[6], w[6];
    #pragma unroll
    for (int k = 0; k < 3; ++k) {
        const int u = 2 * (s + 8 * k) + phi;     // 0..47 (phi=0) / 1..48 (phi=1)
        ex[2*k]   = __ldg(eta + u);     ey[2*k]   = __ldg(eta + Q + u);
        ex[2*k+1] = __ldg(eta + u + 1); ey[2*k+1] = __ldg(eta + Q + u + 1);
        w[2*k]    = __ldg(wts + u);
        w[2*k+1]  = __ldg(wts + u + 1);
    }
    // Tail point (s==0 lane only): q=0 for phi=1, q=48 for phi=0.
    const int qt = phi ? 0 : Q - 1;
    const float ext = __ldg(eta + qt), eyt = __ldg(eta + Q + qt);
    const float wt  = __ldg(wts + qt);

    const int warp_g = (blockIdx.x * TPB + tid) >> 5;
    const int nwarp  = (gridDim.x * TPB) >> 5;
    const int nquad  = (npair + 3) >> 2;

    int  qid   = warp_g;
    bool valid = (qid < nquad);
    int  p     = qid * 4 + g;

    // Loop-invariant pointer strides (hoisted address math).
    const size_t step_b = (size_t)(4 * nwarp) * (size_t)ROW_B;
    char*        outb   = reinterpret_cast<char*>(out_pts)
                        + (size_t)p * (size_t)ROW_B;
    float*       oint   = out_int + p;
    const int    pstep  = 4 * nwarp;

    Params P;
    if (valid && p < npair)
        load_params(means, covars, rots, trans, p, P);

    while (valid) {
        // ---- prefetch next iteration's params ----
        const int  qn    = qid + nwarp;
        const bool vnext = (qn < nquad);
        const int  pn    = p + pstep;
        Params Pn;
        if (vnext && pn < npair)
            load_params(means, covars, rots, trans, pn, Pn);

        // ---- compute current pair ----
        if (p < npair) {
            // Per-pair quadratic coefficients (amortized over 49 points).
            const float det   = P.c.x * P.c.w - P.c.y * P.c.z;
            const float k2    = NEG_HALF_LOG2E_F * __frcp_rn(det);
            const float scale = INV_2PI_F * __frsqrt_rn(det);
            const float Qa = k2 * P.c.w;
            const float Qb = -k2 * (P.c.y + P.c.z);
            const float Qc = k2 * P.c.x;
            const float D  = -fmaf(2.0f * Qa, P.m.x, Qb * P.m.y);
            const float E  = -fmaf(2.0f * Qc, P.m.y, Qb * P.m.x);
            const float F  = fmaf(P.m.x, fmaf(Qa, P.m.x, Qb * P.m.y),
                                  Qc * P.m.y * P.m.y);

            float acc0 = 0.0f, acc1 = 0.0f;

            #pragma unroll
            for (int k = 0; k < 3; ++k) {
                const int j = s + 8 * k;          // float4 slot 0..23
                const float px0 = fmaf(P.r.x, ex[2*k],   fmaf(P.r.y, ey[2*k],   P.t.x));
                const float py0 = fmaf(P.r.z, ex[2*k],   fmaf(P.r.w, ey[2*k],   P.t.y));
                const float px1 = fmaf(P.r.x, ex[2*k+1], fmaf(P.r.y, ey[2*k+1], P.t.x));
                const float py1 = fmaf(P.r.z, ex[2*k+1], fmaf(P.r.w, ey[2*k+1], P.t.y));

                __stcs(reinterpret_cast<float4*>(outb + 8 * phi + 16 * j),
                       make_float4(px0, py0, px1, py1));   // 16B-aligned STG.128

                float t1 = fmaf(Qa, px0, fmaf(Qb, py0, D));
                float t2 = fmaf(Qc, py0, E);
                float arg = fmaf(px0, t1, fmaf(py0, t2, F));
                acc0 = fmaf(w[2*k], exp2f(arg), acc0);

                t1 = fmaf(Qa, px1, fmaf(Qb, py1, D));
                t2 = fmaf(Qc, py1, E);
                arg = fmaf(px1, t1, fmaf(py1, t2, F));
                acc1 = fmaf(w[2*k+1], exp2f(arg), acc1);
            }

            // Scalar tail point (one per pair).
            if (s == 0) {
                const float px = fmaf(P.r.x, ext, fmaf(P.r.y, eyt, P.t.x));
                const float py = fmaf(P.r.z, ext, fmaf(P.r.w, eyt, P.t.y));
                __stcs(reinterpret_cast<float2*>(outb + (phi ? 0 : 8 * (Q - 1))),
                       make_float2(px, py));
                const float t1 = fmaf(Qa, px, fmaf(Qb, py, D));
                const float t2 = fmaf(Qc, py, E);
                const float arg = fmaf(px, t1, fmaf(py, t2, F));
                acc0 = fmaf(wt, exp2f(arg), acc0);
            }

            // Reduce over the 8 lanes of this group.
            float acc = acc0 + acc1;
            const unsigned gmask = 0xFFu << (g * 8);
            acc += __shfl_down_sync(gmask, acc, 4, 8);
            acc += __shfl_down_sync(gmask, acc, 2, 8);
            acc += __shfl_down_sync(gmask, acc, 1, 8);

            if (s == 0)
                *oint = fminf(fmaxf(scale * acc, 0.0f), 1.0f);
        }

        P = Pn; qid = qn; p = pn; valid = vnext;
        outb += step_b; oint += pstep;
    }
}

extern "C" void kernel_launch(void* const* d_in, const int* in_sizes, int n_in,
                              void* d_out, int out_size)
{
    const float* means  = (const float*)d_in[0];
    const float* covars = (const float*)d_in[1];
    const float* rots   = (const float*)d_in[2];
    const float* trans  = (const float*)d_in[3];
    const float* eta    = (const float*)d_in[4];
    const float* wts    = (const float*)d_in[5];

    const int npair = in_sizes[0] / 2;

    float* out_pts = (float*)d_out;
    float* out_int = out_pts + (size_t)npair * (size_t)(2 * Q);

    // ~8 grid-stride iterations per warp at P = 524288.
    const int blocks = 4096;     // 4096 * 128 threads = 16384 warps
    gauss_integral_kernel<<<blocks, TPB>>>(
        means, covars, rots, trans, eta, wts, out_pts, out_int, npair);
}